// round 8
// baseline (speedup 1.0000x reference)
#include <cuda_runtime.h>
#include <cstdint>
#include <cstddef>

#define MAXM 24
#define MAX_B 64
#define MAX_TOTAL (32 * 24576)
#define MAX_PART  16384
#define NGT 4
#define SCH 16
#define TCH 4
#define HBINS 4096
#define CAP 8192

__device__ unsigned long long g_gtpack[MAX_B * MAXM];
__device__ unsigned int       g_hist2[MAX_B * HBINS];
__device__ int                g_npos[MAX_B];
__device__ int                g_pcnt[MAX_B * SCH];
__device__ int                g_cnt[MAX_B];

__device__ unsigned char g_pos[MAX_TOTAL];
__device__ int           g_aidx[MAX_TOTAL];
__device__ float         g_abest[MAX_TOTAL];
__device__ unsigned int  g_negkey[MAX_TOTAL];
__device__ float         g_topk[MAX_B];
__device__ float         g_ploc[MAX_PART];
__device__ float         g_pconf[MAX_PART];

__device__ __forceinline__ unsigned int f2key(float f) {
    unsigned int u = __float_as_uint(f);
    return (u & 0x80000000u) ? ~u : (u | 0x80000000u);
}
__device__ __forceinline__ float key2f(unsigned int k) {
    unsigned int u = (k & 0x80000000u) ? (k & 0x7FFFFFFFu) : ~k;
    return __uint_as_float(u);
}
__device__ __forceinline__ float sl1(float d) {
    d = fabsf(d);
    return d < 1.0f ? 0.5f * d * d : d - 0.5f;
}

// ---------------------------------------------------------------------------
// Launch 1: zero gtpack + hist2.
// ---------------------------------------------------------------------------
__global__ void kzero(int B) {
    int i  = blockIdx.x * blockDim.x + threadIdx.x;
    int st = gridDim.x * blockDim.x;
    for (int k = i; k < MAX_B * MAXM; k += st) g_gtpack[k] = 0ull;
    int n = B * HBINS;
    for (int k = i; k < n; k += st) g_hist2[k] = 0u;
}

// ---------------------------------------------------------------------------
// Launch 2: per-anchor best GT. Grid (SCH, B), 256 threads.
// ---------------------------------------------------------------------------
__global__ void __launch_bounds__(256)
kmatch1(const float* __restrict__ gtb, const float* __restrict__ anc,
        int A, int M, int chunk) {
    int b   = blockIdx.y;
    int tid = threadIdx.x;
    __shared__ float4 sg[MAXM];
    __shared__ float  sga[MAXM];
    __shared__ int    scnt[256];

    if (tid < MAXM) {
        float4 g = make_float4(-9.0f, -9.0f, -9.0f, -9.0f);
        if (tid < M) g = ((const float4*)gtb)[b * M + tid];
        sg[tid]  = g;
        sga[tid] = (g.z - g.x) * (g.w - g.y);
    }
    __syncthreads();

    size_t off = (size_t)b * A;
    int a0 = blockIdx.x * chunk;
    int a1 = a0 + chunk; if (a1 > A) a1 = A;
    int cnt = 0;
    for (int a = a0 + tid; a < a1; a += 256) {
        float4 ac = __ldg(((const float4*)anc) + a);
        float aw2 = ac.z * 0.5f, ah2 = ac.w * 0.5f;
        float ax1 = ac.x - aw2, ay1 = ac.y - ah2;
        float ax2 = ac.x + aw2, ay2 = ac.y + ah2;
        float areaA = (ax2 - ax1) * (ay2 - ay1);
        float best = -1.0f; int bidx = 0;
        #pragma unroll
        for (int j = 0; j < MAXM; j++) {
            float4 g = sg[j];
            float ltx = fmaxf(g.x, ax1), lty = fmaxf(g.y, ay1);
            float rbx = fminf(g.z, ax2), rby = fminf(g.w, ay2);
            float w = fmaxf(rbx - ltx, 0.0f), h = fmaxf(rby - lty, 0.0f);
            float inter = w * h;
            float iou = __fdividef(inter, sga[j] + areaA - inter + 1e-7f);
            bool bw = iou > best;
            best = bw ? iou : best;
            bidx = bw ? j : bidx;
        }
        g_abest[off + a] = best;
        g_aidx[off + a]  = bidx;
        unsigned char p = best > 0.5f ? (unsigned char)1 : (unsigned char)0;
        g_pos[off + a] = p;
        cnt += p;
    }
    scnt[tid] = cnt;
    __syncthreads();
    for (int s = 128; s > 0; s >>= 1) {
        if (tid < s) scnt[tid] += scnt[tid + s];
        __syncthreads();
    }
    if (tid == 0) g_pcnt[b * SCH + blockIdx.x] = scnt[0];
}

// ---------------------------------------------------------------------------
// Launch 3: per-GT best anchor + last-block force-assignment + npos.
// ---------------------------------------------------------------------------
__global__ void __launch_bounds__(256)
kmatch2f(const float* __restrict__ gtb, const float* __restrict__ anc,
         int A, int M, int chunkA, int ngj) {
    int b   = blockIdx.y;
    int tid = threadIdx.x;
    int jg  = blockIdx.x % ngj;
    int tch = blockIdx.x / ngj;
    int j0  = jg * NGT;
    __shared__ float4 sg[NGT];
    __shared__ float  sga[NGT];
    __shared__ unsigned long long sred[256];
    __shared__ int lastFlag;

    if (tid < NGT) {
        int j = j0 + tid;
        float4 g = make_float4(-9.0f, -9.0f, -9.0f, -9.0f);
        if (j < M) g = ((const float4*)gtb)[b * M + j];
        sg[tid]  = g;
        sga[tid] = (g.z - g.x) * (g.w - g.y);
    }
    __syncthreads();

    float bv0 = -1.0f, bv1 = -1.0f, bv2 = -1.0f, bv3 = -1.0f;
    unsigned bi0 = 0, bi1 = 0, bi2 = 0, bi3 = 0;
    float4 g0 = sg[0], g1 = sg[1], g2 = sg[2], g3 = sg[3];
    float a0 = sga[0], a1 = sga[1], a2 = sga[2], a3 = sga[3];

    int as = tch * chunkA;
    int ae = as + chunkA; if (ae > A) ae = A;
    for (int a = as + tid; a < ae; a += 256) {
        float4 ac = __ldg(((const float4*)anc) + a);
        float aw2 = ac.z * 0.5f, ah2 = ac.w * 0.5f;
        float ax1 = ac.x - aw2, ay1 = ac.y - ah2;
        float ax2 = ac.x + aw2, ay2 = ac.y + ah2;
        float areaA = (ax2 - ax1) * (ay2 - ay1);
        #define IOU_OF(G, AREA, BV, BI)                                        \
        {                                                                      \
            float ltx = fmaxf(G.x, ax1), lty = fmaxf(G.y, ay1);                \
            float rbx = fminf(G.z, ax2), rby = fminf(G.w, ay2);                \
            float w = fmaxf(rbx - ltx, 0.0f), h = fmaxf(rby - lty, 0.0f);      \
            float inter = w * h;                                               \
            float iou = __fdividef(inter, AREA + areaA - inter + 1e-7f);       \
            if (iou > BV) { BV = iou; BI = (unsigned)a; }                      \
        }
        IOU_OF(g0, a0, bv0, bi0)
        IOU_OF(g1, a1, bv1, bi1)
        IOU_OF(g2, a2, bv2, bi2)
        IOU_OF(g3, a3, bv3, bi3)
        #undef IOU_OF
    }

    float    bvs[NGT] = {bv0, bv1, bv2, bv3};
    unsigned bis[NGT] = {bi0, bi1, bi2, bi3};
    #pragma unroll
    for (int g = 0; g < NGT; g++) {
        unsigned long long pk =
            ((unsigned long long)__float_as_uint(bvs[g]) << 32) | (unsigned)(~bis[g]);
        sred[tid] = pk;
        __syncthreads();
        for (int s = 128; s > 0; s >>= 1) {
            if (tid < s) {
                unsigned long long o = sred[tid + s];
                if (o > sred[tid]) sred[tid] = o;
            }
            __syncthreads();
        }
        if (tid == 0 && j0 + g < M)
            atomicMax(&g_gtpack[b * MAXM + j0 + g], sred[0]);
        __syncthreads();
    }

    __threadfence();
    if (tid == 0)
        lastFlag = (atomicAdd(&g_cnt[b], 1) == gridDim.x - 1) ? 1 : 0;
    __syncthreads();
    if (lastFlag) {
        if (tid == 0) g_cnt[b] = 0;
        if (tid < 32) {
            int lane = tid;
            size_t off = (size_t)b * A;
            unsigned long long pk = (lane < M) ? g_gtpack[b * MAXM + lane] : 0ull;
            float    v  = __uint_as_float((unsigned)(pk >> 32));
            unsigned ba = ~((unsigned)pk);
            bool valid  = (lane < M) && (v > 1e-5f);

            unsigned key = valid ? ba : (0x80000000u + (unsigned)lane);
            unsigned grp = __match_any_sync(0xffffffffu, key);

            unsigned char oldpos = valid ? g_pos[off + ba] : (unsigned char)1;
            float ab = valid ? g_abest[off + ba] : 1e30f;
            bool over = valid && (ab < v);
            unsigned ovm = __ballot_sync(0xffffffffu, over);
            if (over && (31 - __clz(grp & ovm)) == lane) g_aidx[off + ba] = lane;
            if (valid) g_pos[off + ba] = 1;

            bool newpos = valid && !oldpos && ((__ffs(grp) - 1) == lane);
            unsigned nm = __ballot_sync(0xffffffffu, newpos);

            int pc = (lane < SCH) ? g_pcnt[b * SCH + lane] : 0;
            #pragma unroll
            for (int o = 16; o; o >>= 1) pc += __shfl_xor_sync(0xffffffffu, pc, o);
            if (lane == 0) g_npos[b] = pc + __popc(nm);
        }
    }
}

// ---------------------------------------------------------------------------
// Launch 4 (PROFILED): CE. 256 threads / 128-anchor tile, exp-during-load:
// the tile stores exp(score); phase-2 is pure LDS+FADD (no MUFU chains).
// conf = log(s) - log(e_cls).
// ---------------------------------------------------------------------------
__global__ void __launch_bounds__(256)
kloss81(const float* __restrict__ plocs, const float* __restrict__ scores,
        const float* __restrict__ gtb, const int* __restrict__ gtl,
        const float* __restrict__ anc, int A, int M) {
    const int NC = 81;
    __shared__ float tile[128 * NC];
    __shared__ float sPart[128];
    __shared__ float sL[256], sC[256];

    int b    = blockIdx.y;
    int tid  = threadIdx.x;
    int abase = blockIdx.x * 128;
    int cnt   = A - abase; if (cnt > 128) cnt = 128;
    size_t off  = (size_t)b * A;
    size_t base = (off + (size_t)abase) * NC;
    int nflt = cnt * NC;

    const float* src = scores + base;
    if ((base & 3) == 0) {
        const float4* s4 = (const float4*)src;
        float4* t4 = (float4*)tile;
        int n4 = nflt >> 2;
        for (int i = tid; i < n4; i += 256) {
            float4 v = __ldg(s4 + i);
            v.x = __expf(v.x); v.y = __expf(v.y);
            v.z = __expf(v.z); v.w = __expf(v.w);
            t4[i] = v;
        }
        for (int i = (n4 << 2) + tid; i < nflt; i += 256) tile[i] = __expf(src[i]);
    } else {
        for (int i = tid; i < nflt; i += 256) tile[i] = __expf(__ldg(src + i));
    }
    __syncthreads();

    int r    = tid & 127;
    int half = tid >> 7;
    float mySum = 0.0f;
    if (r < cnt) {
        const float* row = tile + r * NC;
        float s0 = 0, s1 = 0, s2 = 0, s3 = 0;
        if (half == 0) {
            #pragma unroll
            for (int c = 0; c < 40; c += 4) {
                s0 += row[c]; s1 += row[c + 1]; s2 += row[c + 2]; s3 += row[c + 3];
            }
            s0 += row[40];
        } else {
            #pragma unroll
            for (int c = 41; c < 81; c += 4) {
                s0 += row[c]; s1 += row[c + 1]; s2 += row[c + 2]; s3 += row[c + 3];
            }
            sPart[r] = 0.0f;  // placeholder; overwritten below
        }
        mySum = (s0 + s1) + (s2 + s3);
        if (half == 1) sPart[r] = mySum;
    }
    __syncthreads();

    float locSum = 0.0f, confPos = 0.0f;
    if (half == 0 && r < cnt) {
        float s = mySum + sPart[r];
        const float* row = tile + r * NC;
        int a = abase + r;
        unsigned char p = g_pos[off + a];
        int ai = g_aidx[off + a];
        int cls = p ? (__ldg(gtl + (size_t)b * M + ai) + 1) : 0;
        float conf = __logf(s) - __logf(row[cls]);

        g_negkey[off + a] = p ? 0u : f2key(conf);

        if (p) {
            confPos = conf;
            float4 pl  = __ldg(((const float4*)plocs) + off + a);
            float4 ac4 = __ldg(((const float4*)anc) + a);
            float4 g   = __ldg(((const float4*)gtb) + (size_t)b * M + ai);
            float mcx = (g.x + g.z) * 0.5f, mcy = (g.y + g.w) * 0.5f;
            float mw = g.z - g.x, mh = g.w - g.y;
            locSum = sl1(pl.x - (mcx - ac4.x) / ac4.z)
                   + sl1(pl.y - (mcy - ac4.y) / ac4.w)
                   + sl1(pl.z - logf(mw / ac4.z + 1e-7f))
                   + sl1(pl.w - logf(mh / ac4.w + 1e-7f));
        }
    }

    sL[tid] = locSum; sC[tid] = confPos;
    __syncthreads();
    for (int s = 128; s > 0; s >>= 1) {
        if (tid < s) { sL[tid] += sL[tid + s]; sC[tid] += sC[tid + s]; }
        __syncthreads();
    }
    if (tid == 0) {
        int pid = blockIdx.y * gridDim.x + blockIdx.x;
        g_ploc[pid]  = sL[0];
        g_pconf[pid] = sC[0];
    }
}

// Generic fallback (any C), warp-cooperative.
template <int NSEG>
__global__ void __launch_bounds__(256)
klossg(const float* __restrict__ plocs, const float* __restrict__ scores,
       const float* __restrict__ gtb, const int* __restrict__ gtl,
       const float* __restrict__ anc, int A, int M, int C) {
    const float NEG = -1e30f;
    int b    = blockIdx.y;
    int warp = threadIdx.x >> 5;
    int lane = threadIdx.x & 31;
    size_t off = (size_t)b * A;
    int abase = (blockIdx.x * 8 + warp) * 8;
    float locSum = 0.0f, confPos = 0.0f;

    for (int k = 0; k < 8; k++) {
        int a = abase + k;
        if (a >= A) break;
        const float* sp = scores + (off + a) * (size_t)C;
        float v[NSEG]; float m;
        #pragma unroll
        for (int sgi = 0; sgi < NSEG; sgi++) {
            int c = lane + sgi * 32;
            v[sgi] = (c < C) ? __ldg(sp + c) : NEG;
        }
        m = v[0];
        #pragma unroll
        for (int sgi = 1; sgi < NSEG; sgi++) m = fmaxf(m, v[sgi]);
        #pragma unroll
        for (int o = 16; o; o >>= 1) m = fmaxf(m, __shfl_xor_sync(0xffffffffu, m, o));
        float s = 0.0f;
        #pragma unroll
        for (int sgi = 0; sgi < NSEG; sgi++) s += __expf(v[sgi] - m);
        #pragma unroll
        for (int o = 16; o; o >>= 1) s += __shfl_xor_sync(0xffffffffu, s, o);

        unsigned char p = g_pos[off + a];
        int ai = g_aidx[off + a];
        int cls = p ? (__ldg(gtl + (size_t)b * M + ai) + 1) : 0;
        int slot = cls >> 5, src = cls & 31;
        float vv = v[0];
        #pragma unroll
        for (int sgi = 1; sgi < NSEG; sgi++) if (slot == sgi) vv = v[sgi];
        float xt = __shfl_sync(0xffffffffu, vv, src);
        float conf = m + __logf(s) - xt;
        if (lane == 0) {
            g_negkey[off + a] = p ? 0u : f2key(conf);
            if (p) {
                confPos += conf;
                float4 pl  = __ldg(((const float4*)plocs) + off + a);
                float4 ac4 = __ldg(((const float4*)anc) + a);
                float4 g   = __ldg(((const float4*)gtb) + (size_t)b * M + ai);
                float mcx = (g.x + g.z) * 0.5f, mcy = (g.y + g.w) * 0.5f;
                float mw = g.z - g.x, mh = g.w - g.y;
                locSum += sl1(pl.x - (mcx - ac4.x) / ac4.z)
                        + sl1(pl.y - (mcy - ac4.y) / ac4.w)
                        + sl1(pl.z - logf(mw / ac4.z + 1e-7f))
                        + sl1(pl.w - logf(mh / ac4.w + 1e-7f));
            }
        }
    }
    __shared__ float smL[8], smC[8];
    if (lane == 0) { smL[warp] = locSum; smC[warp] = confPos; }
    __syncthreads();
    if (threadIdx.x == 0) {
        float L = 0.0f, Cc = 0.0f;
        #pragma unroll
        for (int i = 0; i < 8; i++) { L += smL[i]; Cc += smC[i]; }
        int pid = blockIdx.y * gridDim.x + blockIdx.x;
        g_ploc[pid]  = L;
        g_pconf[pid] = Cc;
    }
}

// ---------------------------------------------------------------------------
// Launch 5: 4096-bin histogram of keys (key >> 20). Grid (8, B), 256 thr.
// ---------------------------------------------------------------------------
__global__ void __launch_bounds__(256)
khist(int A, int chunk) {
    __shared__ unsigned int sh[HBINS];
    int b   = blockIdx.y;
    int tid = threadIdx.x;
    for (int i = tid; i < HBINS; i += 256) sh[i] = 0u;
    __syncthreads();
    size_t off = (size_t)b * A;
    int a0 = blockIdx.x * chunk;
    int a1 = a0 + chunk; if (a1 > A) a1 = A;
    for (int a = a0 + tid; a < a1; a += 256)
        atomicAdd(&sh[g_negkey[off + a] >> 20], 1u);
    __syncthreads();
    for (int i = tid; i < HBINS; i += 256) {
        unsigned v = sh[i];
        if (v) atomicAdd(&g_hist2[b * HBINS + i], v);
    }
}

// ---------------------------------------------------------------------------
// Launch 6: exact top-k sum. One CTA per batch, 512 threads.
// Suffix-scan the 4096-bin hist -> boundary bin d + kk; single streaming
// pass sums keys above d and compacts bin-d keys; tiny radix finishes.
// ---------------------------------------------------------------------------
__global__ void __launch_bounds__(512)
kselect2(int A) {
    extern __shared__ unsigned int sbuf[];        // CAP keys
    __shared__ unsigned int hist[HBINS];          // 16 KB
    __shared__ unsigned int coarse[512];
    __shared__ float red[512];
    __shared__ unsigned int s_d, s_kk, s_cnt, s_prefix, s_kk2;
    __shared__ unsigned int h2[256];

    int b   = blockIdx.x;
    int tid = threadIdx.x;
    size_t off = (size_t)b * A;

    for (int i = tid; i < HBINS; i += 512) hist[i] = g_hist2[b * HBINS + i];
    __syncthreads();

    int np = g_npos[b];
    int k;
    if (np > 0) { k = 3 * np; int lim = A - np; if (k > lim) k = lim; }
    else        { k = (60 < A) ? 60 : A; }
    if (k <= 0) { if (tid == 0) g_topk[b] = 0.0f; return; }

    // coarse[t] = sum of bins [8t, 8t+8)
    {
        unsigned s = 0;
        #pragma unroll
        for (int j = 0; j < 8; j++) s += hist[tid * 8 + j];
        coarse[tid] = s;
    }
    __syncthreads();
    // inclusive suffix sums
    for (int o = 1; o < 512; o <<= 1) {
        unsigned v = (tid + o < 512) ? coarse[tid + o] : 0u;
        __syncthreads();
        coarse[tid] += v;
        __syncthreads();
    }
    // owner: suf[t] >= k, suf[t+1] < k
    {
        unsigned suf  = coarse[tid];
        unsigned nxt  = (tid < 511) ? coarse[tid + 1] : 0u;
        if (suf >= (unsigned)k && nxt < (unsigned)k) {
            unsigned cum = nxt;
            int d = tid * 8;
            for (int bin = tid * 8 + 7; bin >= tid * 8; bin--) {
                cum += hist[bin];
                if (cum >= (unsigned)k) { d = bin; break; }
            }
            s_d  = (unsigned)d;
            s_kk = (unsigned)k - (cum - hist[d]);
        }
        if (tid == 0) s_cnt = 0u;
    }
    __syncthreads();
    unsigned d  = s_d;
    unsigned kk = s_kk;
    unsigned nBoundary = hist[d];

    // streaming pass: sum above-bin keys, compact boundary-bin keys
    float sum = 0.0f;
    bool fits = nBoundary <= CAP;
    for (int i = tid; i < A; i += 512) {
        unsigned key = g_negkey[off + i];
        unsigned bin = key >> 20;
        if (bin > d) sum += key2f(key);
        else if (bin == d && fits) {
            unsigned idx = atomicAdd(&s_cnt, 1u);
            sbuf[idx] = key;
        }
    }
    __syncthreads();

    unsigned prefix = d << 20, maskHi = 0xFFF00000u;
    if (fits) {
        unsigned n = s_cnt;
        // 3 radix passes over low 20 bits (8, 8, 4)
        #pragma unroll
        for (int p = 0; p < 3; p++) {
            int shift = (p == 0) ? 12 : (p == 1) ? 4 : 0;
            unsigned bmask = (p == 2) ? 15u : 255u;
            int nb = (p == 2) ? 16 : 256;
            if (tid < 256) h2[tid] = 0u;
            __syncthreads();
            for (unsigned i = tid; i < n; i += 512) {
                unsigned key = sbuf[i];
                if ((key & maskHi) == prefix)
                    atomicAdd(&h2[(key >> shift) & bmask], 1u);
            }
            __syncthreads();
            if (tid == 0) {
                unsigned cum = 0; int dd = nb - 1;
                for (; dd >= 0; dd--) { cum += h2[dd]; if (cum >= kk) break; }
                s_kk2    = kk - (cum - h2[dd]);
                s_prefix = prefix | ((unsigned)dd << shift);
            }
            __syncthreads();
            prefix = s_prefix;
            kk     = s_kk2;
            maskHi |= bmask << shift;
            __syncthreads();
        }
        for (unsigned i = tid; i < n; i += 512) {
            unsigned key = sbuf[i];
            if (key > prefix) sum += key2f(key);
        }
    } else {
        // fallback: radix over gmem keys (rare)
        #pragma unroll
        for (int p = 0; p < 3; p++) {
            int shift = (p == 0) ? 12 : (p == 1) ? 4 : 0;
            unsigned bmask = (p == 2) ? 15u : 255u;
            int nb = (p == 2) ? 16 : 256;
            if (tid < 256) h2[tid] = 0u;
            __syncthreads();
            for (int i = tid; i < A; i += 512) {
                unsigned key = g_negkey[off + i];
                if ((key & maskHi) == prefix)
                    atomicAdd(&h2[(key >> shift) & bmask], 1u);
            }
            __syncthreads();
            if (tid == 0) {
                unsigned cum = 0; int dd = nb - 1;
                for (; dd >= 0; dd--) { cum += h2[dd]; if (cum >= kk) break; }
                s_kk2    = kk - (cum - h2[dd]);
                s_prefix = prefix | ((unsigned)dd << shift);
            }
            __syncthreads();
            prefix = s_prefix;
            kk     = s_kk2;
            maskHi |= bmask << shift;
            __syncthreads();
        }
        for (int i = tid; i < A; i += 512) {
            unsigned key = g_negkey[off + i];
            if ((key >> 20) == d && key > prefix) sum += key2f(key);
        }
    }
    if (tid == 0) sum += (float)kk * key2f(prefix);

    red[tid] = sum;
    __syncthreads();
    for (int s = 256; s > 0; s >>= 1) {
        if (tid < s) red[tid] += red[tid + s];
        __syncthreads();
    }
    if (tid == 0) g_topk[b] = red[0];
}

// ---------------------------------------------------------------------------
// Launch 7: final reduction.
// ---------------------------------------------------------------------------
__global__ void kfinal(float* __restrict__ out, int P, int B) {
    __shared__ float s1[512], s2[512];
    __shared__ int   s3[512];
    int tid = threadIdx.x;
    float L = 0.0f, Cc = 0.0f; int np = 0;
    for (int i = tid; i < P; i += 512) { L += g_ploc[i]; Cc += g_pconf[i]; }
    for (int i = tid; i < B; i += 512) { Cc += g_topk[i]; np += g_npos[i]; }
    s1[tid] = L; s2[tid] = Cc; s3[tid] = np;
    __syncthreads();
    for (int s = 256; s > 0; s >>= 1) {
        if (tid < s) { s1[tid] += s1[tid+s]; s2[tid] += s2[tid+s]; s3[tid] += s3[tid+s]; }
        __syncthreads();
    }
    if (tid == 0) {
        float loc = s1[0], conf = s2[0];
        float denom = (float)(s3[0] > 1 ? s3[0] : 1);
        out[0] = (loc + conf) / denom;
        out[1] = loc / denom;
        out[2] = conf / denom;
    }
}

// ---------------------------------------------------------------------------
extern "C" void kernel_launch(void* const* d_in, const int* in_sizes, int n_in,
                              void* d_out, int out_size) {
    const float* plocs  = (const float*)d_in[0];
    const float* scores = (const float*)d_in[1];
    const float* gtb    = (const float*)d_in[2];
    const int*   gtl    = (const int*)d_in[3];
    const float* anc    = (const float*)d_in[4];

    int A = in_sizes[4] / 4;
    int B = in_sizes[0] / (4 * A);
    int C = (int)((long long)in_sizes[1] / ((long long)A * B));
    int M = in_sizes[3] / B;

    kzero<<<128, 256>>>(B);                                          // 1

    int chunk = (A + SCH - 1) / SCH;
    kmatch1<<<dim3(SCH, B), 256>>>(gtb, anc, A, M, chunk);           // 2

    int ngj = (M + NGT - 1) / NGT;
    int chunkA = (A + TCH - 1) / TCH;
    kmatch2f<<<dim3(ngj * TCH, B), 256>>>(gtb, anc, A, M, chunkA, ngj); // 3

    int gx;
    if (C == 81) {
        gx = (A + 127) / 128;
        kloss81<<<dim3(gx, B), 256>>>(plocs, scores, gtb, gtl, anc, A, M); // 4 (profiled)
    } else {
        gx = (A + 63) / 64;
        if (C <= 96) klossg<3><<<dim3(gx, B), 256>>>(plocs, scores, gtb, gtl, anc, A, M, C);
        else         klossg<4><<<dim3(gx, B), 256>>>(plocs, scores, gtb, gtl, anc, A, M, C);
    }

    int hch = (A + 7) / 8;
    khist<<<dim3(8, B), 256>>>(A, hch);                              // 5

    cudaFuncSetAttribute(kselect2, cudaFuncAttributeMaxDynamicSharedMemorySize,
                         CAP * 4 + 1024);
    kselect2<<<B, 512, CAP * 4>>>(A);                                // 6

    int P = gx * B;
    kfinal<<<1, 512>>>((float*)d_out, P, B);                         // 7
}

// round 9
// speedup vs baseline: 1.0108x; 1.0108x over previous
#include <cuda_runtime.h>
#include <cstdint>
#include <cstddef>

#define MAXM 24
#define MAX_B 64
#define MAX_TOTAL (32 * 24576)
#define NGT 4
#define SCH 16
#define TCH 4
#define FCH 8
#define HBINS 4096
#define CAP 8192

__device__ unsigned long long g_gtpack[MAX_B * MAXM];   // self-cleaning
__device__ unsigned int       g_hist2[MAX_B * HBINS];   // self-cleaning
__device__ int                g_npos[MAX_B];
__device__ int                g_pcnt[MAX_B * SCH];
__device__ int                g_cnt[MAX_B];             // self-cleaning

__device__ unsigned char g_pos[MAX_TOTAL];
__device__ int           g_aidx[MAX_TOTAL];
__device__ float         g_abest[MAX_TOTAL];
__device__ unsigned int  g_negkey[MAX_TOTAL];
__device__ float         g_topk[MAX_B];
__device__ float         g_ploc[MAX_B * 512];    // generic (C!=81) path partials
__device__ float         g_pconf[MAX_B * 512];
__device__ float         g_ploc2[MAX_B * FCH];   // kfixhist partials
__device__ float         g_pconf2[MAX_B * FCH];

__device__ __forceinline__ unsigned int f2key(float f) {
    unsigned int u = __float_as_uint(f);
    return (u & 0x80000000u) ? ~u : (u | 0x80000000u);
}
__device__ __forceinline__ float key2f(unsigned int k) {
    unsigned int u = (k & 0x80000000u) ? (k & 0x7FFFFFFFu) : ~k;
    return __uint_as_float(u);
}
__device__ __forceinline__ float sl1(float d) {
    d = fabsf(d);
    return d < 1.0f ? 0.5f * d * d : d - 0.5f;
}

// Force-assignment, run by 32 threads of the LAST match block per batch.
// Order-independent (pos 0->1 only; aidx last-j = max-j; override vs ORIGINAL
// a_best_iou). Self-cleans g_gtpack.
__device__ __forceinline__ void do_force(int lane, int b, int A, int M) {
    size_t off = (size_t)b * A;
    unsigned long long pk = (lane < M) ? g_gtpack[b * MAXM + lane] : 0ull;
    if (lane < MAXM) g_gtpack[b * MAXM + lane] = 0ull;
    float    v  = __uint_as_float((unsigned)(pk >> 32));
    unsigned ba = ~((unsigned)pk);
    bool valid  = (lane < M) && (v > 1e-5f);

    unsigned key = valid ? ba : (0x80000000u + (unsigned)lane);
    unsigned grp = __match_any_sync(0xffffffffu, key);

    unsigned char oldpos = valid ? g_pos[off + ba] : (unsigned char)1;
    float ab = valid ? g_abest[off + ba] : 1e30f;
    bool over = valid && (ab < v);
    unsigned ovm = __ballot_sync(0xffffffffu, over);
    if (over && (31 - __clz(grp & ovm)) == lane) g_aidx[off + ba] = lane;
    if (valid) g_pos[off + ba] = 1;

    bool newpos = valid && !oldpos && ((__ffs(grp) - 1) == lane);
    unsigned nm = __ballot_sync(0xffffffffu, newpos);

    int pc = (lane < SCH) ? g_pcnt[b * SCH + lane] : 0;
    #pragma unroll
    for (int o = 16; o; o >>= 1) pc += __shfl_xor_sync(0xffffffffu, pc, o);
    if (lane == 0) g_npos[b] = pc + __popc(nm);
}

// ---------------------------------------------------------------------------
// kbig: heterogeneous blocks. Every S-th block (while supply lasts) is a
// MATCH block (kmatch1 / kmatch2 + last-block force); the rest are LOSS
// blocks (stream scores, exp-sum, write negkey assuming negative class 0 —
// no dependence on matching).
// ---------------------------------------------------------------------------
__global__ void __launch_bounds__(256, 5)
kbig(const float* __restrict__ scores, const float* __restrict__ gtb,
     const float* __restrict__ anc, int A, int M, int gx,
     int chunk1, int chunkA, int ngj, int S, int Mt, int M1, int Tm) {
    __shared__ union {
        struct { float tile[128 * 81]; float sPart[128]; } ls;
        struct { float4 sg[MAXM]; float sga[MAXM]; int scnt[256]; int lastFlag; } m1;
        struct { float4 sg[NGT]; float sga[NGT]; unsigned long long sred[256]; int lastFlag; } m2;
    } sm;

    int p   = blockIdx.x;
    int tid = threadIdx.x;
    int lim = S * Mt;
    bool isMatch = (p < lim) && (p % S == 0) && (p / S < Mt);
    int idx = isMatch ? (p / S) : ((p < lim) ? (p - p / S - 1) : (p - Mt));

    if (isMatch && idx < M1) {
        // ---------------- match1: per-anchor best GT ----------------
        int b  = idx / SCH;
        int bx = idx % SCH;
        if (tid < MAXM) {
            float4 g = make_float4(-9.0f, -9.0f, -9.0f, -9.0f);
            if (tid < M) g = ((const float4*)gtb)[b * M + tid];
            sm.m1.sg[tid]  = g;
            sm.m1.sga[tid] = (g.z - g.x) * (g.w - g.y);
        }
        __syncthreads();
        size_t off = (size_t)b * A;
        int a0 = bx * chunk1;
        int a1 = a0 + chunk1; if (a1 > A) a1 = A;
        int cnt = 0;
        for (int a = a0 + tid; a < a1; a += 256) {
            float4 ac = __ldg(((const float4*)anc) + a);
            float aw2 = ac.z * 0.5f, ah2 = ac.w * 0.5f;
            float ax1 = ac.x - aw2, ay1 = ac.y - ah2;
            float ax2 = ac.x + aw2, ay2 = ac.y + ah2;
            float areaA = (ax2 - ax1) * (ay2 - ay1);
            float best = -1.0f; int bidx = 0;
            #pragma unroll
            for (int j = 0; j < MAXM; j++) {
                float4 g = sm.m1.sg[j];
                float ltx = fmaxf(g.x, ax1), lty = fmaxf(g.y, ay1);
                float rbx = fminf(g.z, ax2), rby = fminf(g.w, ay2);
                float w = fmaxf(rbx - ltx, 0.0f), h = fmaxf(rby - lty, 0.0f);
                float inter = w * h;
                float iou = __fdividef(inter, sm.m1.sga[j] + areaA - inter + 1e-7f);
                bool bw = iou > best;
                best = bw ? iou : best;
                bidx = bw ? j : bidx;
            }
            g_abest[off + a] = best;
            g_aidx[off + a]  = bidx;
            unsigned char pp = best > 0.5f ? (unsigned char)1 : (unsigned char)0;
            g_pos[off + a] = pp;
            cnt += pp;
        }
        sm.m1.scnt[tid] = cnt;
        __syncthreads();
        for (int s = 128; s > 0; s >>= 1) {
            if (tid < s) sm.m1.scnt[tid] += sm.m1.scnt[tid + s];
            __syncthreads();
        }
        if (tid == 0) g_pcnt[b * SCH + bx] = sm.m1.scnt[0];
        __threadfence();
        if (tid == 0)
            sm.m1.lastFlag = (atomicAdd(&g_cnt[b], 1) == Tm - 1) ? 1 : 0;
        __syncthreads();
        if (sm.m1.lastFlag) {
            if (tid == 0) g_cnt[b] = 0;
            if (tid < 32) do_force(tid, b, A, M);
        }
    } else if (isMatch) {
        // ---------------- match2: per-GT best anchor ----------------
        int idx2 = idx - M1;
        int pb   = ngj * TCH;
        int b    = idx2 / pb;
        int q    = idx2 % pb;
        int jg   = q % ngj;
        int tch  = q / ngj;
        int j0   = jg * NGT;
        if (tid < NGT) {
            int j = j0 + tid;
            float4 g = make_float4(-9.0f, -9.0f, -9.0f, -9.0f);
            if (j < M) g = ((const float4*)gtb)[b * M + j];
            sm.m2.sg[tid]  = g;
            sm.m2.sga[tid] = (g.z - g.x) * (g.w - g.y);
        }
        __syncthreads();
        float bv0 = -1.0f, bv1 = -1.0f, bv2 = -1.0f, bv3 = -1.0f;
        unsigned bi0 = 0, bi1 = 0, bi2 = 0, bi3 = 0;
        float4 g0 = sm.m2.sg[0], g1 = sm.m2.sg[1], g2 = sm.m2.sg[2], g3 = sm.m2.sg[3];
        float a0v = sm.m2.sga[0], a1v = sm.m2.sga[1], a2v = sm.m2.sga[2], a3v = sm.m2.sga[3];

        int as = tch * chunkA;
        int ae = as + chunkA; if (ae > A) ae = A;
        for (int a = as + tid; a < ae; a += 256) {
            float4 ac = __ldg(((const float4*)anc) + a);
            float aw2 = ac.z * 0.5f, ah2 = ac.w * 0.5f;
            float ax1 = ac.x - aw2, ay1 = ac.y - ah2;
            float ax2 = ac.x + aw2, ay2 = ac.y + ah2;
            float areaA = (ax2 - ax1) * (ay2 - ay1);
            #define IOU_OF(G, AREA, BV, BI)                                    \
            {                                                                  \
                float ltx = fmaxf(G.x, ax1), lty = fmaxf(G.y, ay1);            \
                float rbx = fminf(G.z, ax2), rby = fminf(G.w, ay2);            \
                float w = fmaxf(rbx - ltx, 0.0f), h = fmaxf(rby - lty, 0.0f);  \
                float inter = w * h;                                           \
                float iou = __fdividef(inter, AREA + areaA - inter + 1e-7f);   \
                if (iou > BV) { BV = iou; BI = (unsigned)a; }                  \
            }
            IOU_OF(g0, a0v, bv0, bi0)
            IOU_OF(g1, a1v, bv1, bi1)
            IOU_OF(g2, a2v, bv2, bi2)
            IOU_OF(g3, a3v, bv3, bi3)
            #undef IOU_OF
        }
        float    bvs[NGT] = {bv0, bv1, bv2, bv3};
        unsigned bis[NGT] = {bi0, bi1, bi2, bi3};
        #pragma unroll
        for (int g = 0; g < NGT; g++) {
            unsigned long long pk =
                ((unsigned long long)__float_as_uint(bvs[g]) << 32) | (unsigned)(~bis[g]);
            sm.m2.sred[tid] = pk;
            __syncthreads();
            for (int s = 128; s > 0; s >>= 1) {
                if (tid < s) {
                    unsigned long long o = sm.m2.sred[tid + s];
                    if (o > sm.m2.sred[tid]) sm.m2.sred[tid] = o;
                }
                __syncthreads();
            }
            if (tid == 0 && j0 + g < M)
                atomicMax(&g_gtpack[b * MAXM + j0 + g], sm.m2.sred[0]);
            __syncthreads();
        }
        __threadfence();
        if (tid == 0)
            sm.m2.lastFlag = (atomicAdd(&g_cnt[b], 1) == Tm - 1) ? 1 : 0;
        __syncthreads();
        if (sm.m2.lastFlag) {
            if (tid == 0) g_cnt[b] = 0;
            if (tid < 32) do_force(tid, b, A, M);
        }
    } else {
        // ---------------- loss: exp-sum + negkey (class-0 conf) ----------
        const int NC = 81;
        int b = idx / gx;
        int t = idx % gx;
        int abase = t * 128;
        int cnt = A - abase; if (cnt > 128) cnt = 128;
        size_t off  = (size_t)b * A;
        size_t base = (off + (size_t)abase) * NC;
        int nflt = cnt * NC;
        float* tile = sm.ls.tile;

        const float* src = scores + base;
        if ((base & 3) == 0) {
            const float4* s4 = (const float4*)src;
            float4* t4 = (float4*)tile;
            int n4 = nflt >> 2;
            for (int i = tid; i < n4; i += 256) {
                float4 v = __ldg(s4 + i);
                v.x = __expf(v.x); v.y = __expf(v.y);
                v.z = __expf(v.z); v.w = __expf(v.w);
                t4[i] = v;
            }
            for (int i = (n4 << 2) + tid; i < nflt; i += 256) tile[i] = __expf(src[i]);
        } else {
            for (int i = tid; i < nflt; i += 256) tile[i] = __expf(__ldg(src + i));
        }
        __syncthreads();

        int r    = tid & 127;
        int half = tid >> 7;
        float mySum = 0.0f;
        if (r < cnt) {
            const float* row = tile + r * NC;
            float s0 = 0, s1 = 0, s2 = 0, s3 = 0;
            if (half == 0) {
                #pragma unroll
                for (int c = 0; c < 40; c += 4) {
                    s0 += row[c]; s1 += row[c + 1]; s2 += row[c + 2]; s3 += row[c + 3];
                }
                s0 += row[40];
            } else {
                #pragma unroll
                for (int c = 41; c < 81; c += 4) {
                    s0 += row[c]; s1 += row[c + 1]; s2 += row[c + 2]; s3 += row[c + 3];
                }
            }
            mySum = (s0 + s1) + (s2 + s3);
            if (half == 1) sm.ls.sPart[r] = mySum;
        }
        __syncthreads();
        if (half == 0 && r < cnt) {
            float s = mySum + sm.ls.sPart[r];
            float conf0 = __logf(s) - __logf(tile[r * NC]);   // cls = 0
            g_negkey[off + abase + r] = f2key(conf0);
        }
    }
}

// ---------------------------------------------------------------------------
// kfixhist: fix positives (negkey->0, true conf, loc loss) + 4096-bin hist.
// Grid (FCH, B), 256 threads.
// ---------------------------------------------------------------------------
__global__ void __launch_bounds__(256)
kfixhist(const float* __restrict__ scores, const float* __restrict__ plocs,
         const float* __restrict__ gtb, const int* __restrict__ gtl,
         const float* __restrict__ anc, int A, int M, int C, int chunk) {
    __shared__ unsigned int sh[HBINS];
    __shared__ float sL[256], sC[256];
    int b   = blockIdx.y;
    int tid = threadIdx.x;
    for (int i = tid; i < HBINS; i += 256) sh[i] = 0u;
    __syncthreads();

    size_t off = (size_t)b * A;
    int a0 = blockIdx.x * chunk;
    int a1 = a0 + chunk; if (a1 > A) a1 = A;
    float loc = 0.0f, cp = 0.0f;
    for (int a = a0 + tid; a < a1; a += 256) {
        unsigned key = g_negkey[off + a];
        unsigned char p = g_pos[off + a];
        unsigned bin = 0;
        if (!p) bin = key >> 20;
        else if (key) {            // C==81 path: positives carry conf0 key
            g_negkey[off + a] = 0u;
            int ai  = g_aidx[off + a];
            int cls = __ldg(gtl + (size_t)b * M + ai) + 1;
            const float* sp = scores + (off + a) * (size_t)C;
            float conf = key2f(key) + __ldg(sp) - __ldg(sp + cls);
            cp += conf;
            float4 pl  = __ldg(((const float4*)plocs) + off + a);
            float4 ac4 = __ldg(((const float4*)anc) + a);
            float4 g   = __ldg(((const float4*)gtb) + (size_t)b * M + ai);
            float mcx = (g.x + g.z) * 0.5f, mcy = (g.y + g.w) * 0.5f;
            float mw = g.z - g.x, mh = g.w - g.y;
            loc += sl1(pl.x - (mcx - ac4.x) / ac4.z)
                 + sl1(pl.y - (mcy - ac4.y) / ac4.w)
                 + sl1(pl.z - logf(mw / ac4.z + 1e-7f))
                 + sl1(pl.w - logf(mh / ac4.w + 1e-7f));
        }
        atomicAdd(&sh[bin], 1u);
    }
    __syncthreads();
    for (int i = tid; i < HBINS; i += 256) {
        unsigned v = sh[i];
        if (v) atomicAdd(&g_hist2[b * HBINS + i], v);
    }
    sL[tid] = loc; sC[tid] = cp;
    __syncthreads();
    for (int s = 128; s > 0; s >>= 1) {
        if (tid < s) { sL[tid] += sL[tid + s]; sC[tid] += sC[tid + s]; }
        __syncthreads();
    }
    if (tid == 0) {
        int pid = b * FCH + blockIdx.x;
        g_ploc2[pid]  = sL[0];
        g_pconf2[pid] = sC[0];
    }
}

// Generic fallback (C != 81): warp-cooperative CE writing final negkeys +
// partials to g_ploc/g_pconf.
template <int NSEG>
__global__ void __launch_bounds__(256)
klossg(const float* __restrict__ plocs, const float* __restrict__ scores,
       const float* __restrict__ gtb, const int* __restrict__ gtl,
       const float* __restrict__ anc, int A, int M, int C) {
    const float NEG = -1e30f;
    int b    = blockIdx.y;
    int warp = threadIdx.x >> 5;
    int lane = threadIdx.x & 31;
    size_t off = (size_t)b * A;
    int abase = (blockIdx.x * 8 + warp) * 8;
    float locSum = 0.0f, confPos = 0.0f;

    for (int k = 0; k < 8; k++) {
        int a = abase + k;
        if (a >= A) break;
        const float* sp = scores + (off + a) * (size_t)C;
        float v[NSEG]; float m;
        #pragma unroll
        for (int sgi = 0; sgi < NSEG; sgi++) {
            int c = lane + sgi * 32;
            v[sgi] = (c < C) ? __ldg(sp + c) : NEG;
        }
        m = v[0];
        #pragma unroll
        for (int sgi = 1; sgi < NSEG; sgi++) m = fmaxf(m, v[sgi]);
        #pragma unroll
        for (int o = 16; o; o >>= 1) m = fmaxf(m, __shfl_xor_sync(0xffffffffu, m, o));
        float s = 0.0f;
        #pragma unroll
        for (int sgi = 0; sgi < NSEG; sgi++) s += __expf(v[sgi] - m);
        #pragma unroll
        for (int o = 16; o; o >>= 1) s += __shfl_xor_sync(0xffffffffu, s, o);

        unsigned char p = g_pos[off + a];
        int ai = g_aidx[off + a];
        int cls = p ? (__ldg(gtl + (size_t)b * M + ai) + 1) : 0;
        int slot = cls >> 5, src = cls & 31;
        float vv = v[0];
        #pragma unroll
        for (int sgi = 1; sgi < NSEG; sgi++) if (slot == sgi) vv = v[sgi];
        float xt = __shfl_sync(0xffffffffu, vv, src);
        float conf = m + __logf(s) - xt;
        if (lane == 0) {
            g_negkey[off + a] = p ? 0u : f2key(conf);
            if (p) {
                confPos += conf;
                float4 pl  = __ldg(((const float4*)plocs) + off + a);
                float4 ac4 = __ldg(((const float4*)anc) + a);
                float4 g   = __ldg(((const float4*)gtb) + (size_t)b * M + ai);
                float mcx = (g.x + g.z) * 0.5f, mcy = (g.y + g.w) * 0.5f;
                float mw = g.z - g.x, mh = g.w - g.y;
                locSum += sl1(pl.x - (mcx - ac4.x) / ac4.z)
                        + sl1(pl.y - (mcy - ac4.y) / ac4.w)
                        + sl1(pl.z - logf(mw / ac4.z + 1e-7f))
                        + sl1(pl.w - logf(mh / ac4.w + 1e-7f));
            }
        }
    }
    __shared__ float smL[8], smC[8];
    if (lane == 0) { smL[warp] = locSum; smC[warp] = confPos; }
    __syncthreads();
    if (threadIdx.x == 0) {
        float L = 0.0f, Cc = 0.0f;
        #pragma unroll
        for (int i = 0; i < 8; i++) { L += smL[i]; Cc += smC[i]; }
        g_ploc[blockIdx.y * gridDim.x + blockIdx.x]  = L;
        g_pconf[blockIdx.y * gridDim.x + blockIdx.x] = Cc;
    }
}

// ---------------------------------------------------------------------------
// kselect2: exact top-k sum (suffix-scan over 4096-bin hist + compaction +
// tiny radix). Self-cleans g_hist2.
// ---------------------------------------------------------------------------
__global__ void __launch_bounds__(512)
kselect2(int A) {
    extern __shared__ unsigned int sbuf[];
    __shared__ unsigned int hist[HBINS];
    __shared__ unsigned int coarse[512];
    __shared__ float red[512];
    __shared__ unsigned int s_d, s_kk, s_cnt, s_prefix, s_kk2;
    __shared__ unsigned int h2[256];

    int b   = blockIdx.x;
    int tid = threadIdx.x;
    size_t off = (size_t)b * A;

    for (int i = tid; i < HBINS; i += 512) {
        hist[i] = g_hist2[b * HBINS + i];
        g_hist2[b * HBINS + i] = 0u;    // self-clean for next replay
    }
    __syncthreads();

    int np = g_npos[b];
    int k;
    if (np > 0) { k = 3 * np; int lim = A - np; if (k > lim) k = lim; }
    else        { k = (60 < A) ? 60 : A; }
    if (k <= 0) { if (tid == 0) g_topk[b] = 0.0f; return; }

    {
        unsigned s = 0;
        #pragma unroll
        for (int j = 0; j < 8; j++) s += hist[tid * 8 + j];
        coarse[tid] = s;
    }
    __syncthreads();
    for (int o = 1; o < 512; o <<= 1) {
        unsigned v = (tid + o < 512) ? coarse[tid + o] : 0u;
        __syncthreads();
        coarse[tid] += v;
        __syncthreads();
    }
    {
        unsigned suf = coarse[tid];
        unsigned nxt = (tid < 511) ? coarse[tid + 1] : 0u;
        if (suf >= (unsigned)k && nxt < (unsigned)k) {
            unsigned cum = nxt;
            int d = tid * 8;
            for (int bin = tid * 8 + 7; bin >= tid * 8; bin--) {
                cum += hist[bin];
                if (cum >= (unsigned)k) { d = bin; break; }
            }
            s_d  = (unsigned)d;
            s_kk = (unsigned)k - (cum - hist[d]);
        }
        if (tid == 0) s_cnt = 0u;
    }
    __syncthreads();
    unsigned d  = s_d;
    unsigned kk = s_kk;
    unsigned nBoundary = hist[d];

    float sum = 0.0f;
    bool fits = nBoundary <= CAP;
    for (int i = tid; i < A; i += 512) {
        unsigned key = g_negkey[off + i];
        unsigned bin = key >> 20;
        if (bin > d) sum += key2f(key);
        else if (bin == d && fits) {
            unsigned idx = atomicAdd(&s_cnt, 1u);
            sbuf[idx] = key;
        }
    }
    __syncthreads();

    unsigned prefix = d << 20, maskHi = 0xFFF00000u;
    if (fits) {
        unsigned n = s_cnt;
        #pragma unroll
        for (int p = 0; p < 3; p++) {
            int shift = (p == 0) ? 12 : (p == 1) ? 4 : 0;
            unsigned bmask = (p == 2) ? 15u : 255u;
            int nb = (p == 2) ? 16 : 256;
            if (tid < 256) h2[tid] = 0u;
            __syncthreads();
            for (unsigned i = tid; i < n; i += 512) {
                unsigned key = sbuf[i];
                if ((key & maskHi) == prefix)
                    atomicAdd(&h2[(key >> shift) & bmask], 1u);
            }
            __syncthreads();
            if (tid == 0) {
                unsigned cum = 0; int dd = nb - 1;
                for (; dd >= 0; dd--) { cum += h2[dd]; if (cum >= kk) break; }
                s_kk2    = kk - (cum - h2[dd]);
                s_prefix = prefix | ((unsigned)dd << shift);
            }
            __syncthreads();
            prefix = s_prefix;
            kk     = s_kk2;
            maskHi |= bmask << shift;
            __syncthreads();
        }
        for (unsigned i = tid; i < n; i += 512) {
            unsigned key = sbuf[i];
            if (key > prefix) sum += key2f(key);
        }
    } else {
        #pragma unroll
        for (int p = 0; p < 3; p++) {
            int shift = (p == 0) ? 12 : (p == 1) ? 4 : 0;
            unsigned bmask = (p == 2) ? 15u : 255u;
            int nb = (p == 2) ? 16 : 256;
            if (tid < 256) h2[tid] = 0u;
            __syncthreads();
            for (int i = tid; i < A; i += 512) {
                unsigned key = g_negkey[off + i];
                if ((key & maskHi) == prefix)
                    atomicAdd(&h2[(key >> shift) & bmask], 1u);
            }
            __syncthreads();
            if (tid == 0) {
                unsigned cum = 0; int dd = nb - 1;
                for (; dd >= 0; dd--) { cum += h2[dd]; if (cum >= kk) break; }
                s_kk2    = kk - (cum - h2[dd]);
                s_prefix = prefix | ((unsigned)dd << shift);
            }
            __syncthreads();
            prefix = s_prefix;
            kk     = s_kk2;
            maskHi |= bmask << shift;
            __syncthreads();
        }
        for (int i = tid; i < A; i += 512) {
            unsigned key = g_negkey[off + i];
            if ((key >> 20) == d && key > prefix) sum += key2f(key);
        }
    }
    if (tid == 0) sum += (float)kk * key2f(prefix);

    red[tid] = sum;
    __syncthreads();
    for (int s = 256; s > 0; s >>= 1) {
        if (tid < s) red[tid] += red[tid + s];
        __syncthreads();
    }
    if (tid == 0) g_topk[b] = red[0];
}

// ---------------------------------------------------------------------------
__global__ void knop() {
    if (threadIdx.x < MAX_B) g_cnt[threadIdx.x] = 0;   // harmless safety zero
}

__global__ void kfinal(float* __restrict__ out, int P1, int P2, int B) {
    __shared__ float s1[512], s2[512];
    __shared__ int   s3[512];
    int tid = threadIdx.x;
    float L = 0.0f, Cc = 0.0f; int np = 0;
    for (int i = tid; i < P1; i += 512) { L += g_ploc[i];  Cc += g_pconf[i];  }
    for (int i = tid; i < P2; i += 512) { L += g_ploc2[i]; Cc += g_pconf2[i]; }
    for (int i = tid; i < B;  i += 512) { Cc += g_topk[i]; np += g_npos[i];   }
    s1[tid] = L; s2[tid] = Cc; s3[tid] = np;
    __syncthreads();
    for (int s = 256; s > 0; s >>= 1) {
        if (tid < s) { s1[tid] += s1[tid+s]; s2[tid] += s2[tid+s]; s3[tid] += s3[tid+s]; }
        __syncthreads();
    }
    if (tid == 0) {
        float loc = s1[0], conf = s2[0];
        float denom = (float)(s3[0] > 1 ? s3[0] : 1);
        out[0] = (loc + conf) / denom;
        out[1] = loc / denom;
        out[2] = conf / denom;
    }
}

// ---------------------------------------------------------------------------
extern "C" void kernel_launch(void* const* d_in, const int* in_sizes, int n_in,
                              void* d_out, int out_size) {
    const float* plocs  = (const float*)d_in[0];
    const float* scores = (const float*)d_in[1];
    const float* gtb    = (const float*)d_in[2];
    const int*   gtl    = (const int*)d_in[3];
    const float* anc    = (const float*)d_in[4];

    int A = in_sizes[4] / 4;
    int B = in_sizes[0] / (4 * A);
    int C = (int)((long long)in_sizes[1] / ((long long)A * B));
    int M = in_sizes[3] / B;

    int gx81   = (A + 127) / 128;
    int L      = (C == 81) ? gx81 * B : 0;
    int ngj    = (M + NGT - 1) / NGT;
    int Tm     = SCH + ngj * TCH;           // match blocks per batch
    int Mt     = Tm * B;
    int total  = L + Mt;
    int S      = total / Mt; if (S < 1) S = 1;
    int chunk1 = (A + SCH - 1) / SCH;
    int chunkA = (A + TCH - 1) / TCH;
    int M1     = SCH * B;

    knop<<<1, 64>>>();                                               // 1
    kbig<<<total, 256>>>(scores, gtb, anc, A, M, gx81,
                         chunk1, chunkA, ngj, S, Mt, M1, Tm);        // 2

    int P1 = 0;
    if (C != 81) {
        int gxg = (A + 63) / 64;
        if (C <= 96) klossg<3><<<dim3(gxg, B), 256>>>(plocs, scores, gtb, gtl, anc, A, M, C);
        else         klossg<4><<<dim3(gxg, B), 256>>>(plocs, scores, gtb, gtl, anc, A, M, C);
        P1 = gxg * B;
    }

    int fch = (A + FCH - 1) / FCH;
    kfixhist<<<dim3(FCH, B), 256>>>(scores, plocs, gtb, gtl, anc, A, M, C, fch); // 3

    cudaFuncSetAttribute(kselect2, cudaFuncAttributeMaxDynamicSharedMemorySize,
                         CAP * 4 + 1024);
    kselect2<<<B, 512, CAP * 4>>>(A);                                // 4 (profiled)

    kfinal<<<1, 512>>>((float*)d_out, P1, FCH * B, B);               // 5
}

// round 10
// speedup vs baseline: 1.1499x; 1.1375x over previous
#include <cuda_runtime.h>
#include <cstdint>
#include <cstddef>

#define MAXM 24
#define MAX_B 64
#define MAX_TOTAL (32 * 24576)
#define NGT 4
#define SCH 16
#define TCH 4
#define FCH 16
#define HBINS 4096
#define CAP 8192

__device__ unsigned long long g_gtpack[MAX_B * MAXM];   // self-cleaning
__device__ unsigned int       g_hist2[MAX_B * HBINS];   // self-cleaning
__device__ int                g_npos[MAX_B];
__device__ int                g_pcnt[MAX_B * SCH];
__device__ int                g_cnt[MAX_B];             // self-cleaning

__device__ unsigned char g_pos[MAX_TOTAL];
__device__ int           g_aidx[MAX_TOTAL];
__device__ float         g_abest[MAX_TOTAL];
__device__ unsigned int  g_negkey[MAX_TOTAL];
__device__ float         g_topk[MAX_B];
__device__ float         g_ploc[MAX_B * 512];
__device__ float         g_pconf[MAX_B * 512];
__device__ float         g_ploc2[MAX_B * FCH];
__device__ float         g_pconf2[MAX_B * FCH];

__device__ __forceinline__ unsigned int f2key(float f) {
    unsigned int u = __float_as_uint(f);
    return (u & 0x80000000u) ? ~u : (u | 0x80000000u);
}
__device__ __forceinline__ float key2f(unsigned int k) {
    unsigned int u = (k & 0x80000000u) ? (k & 0x7FFFFFFFu) : ~k;
    return __uint_as_float(u);
}
__device__ __forceinline__ float sl1(float d) {
    d = fabsf(d);
    return d < 1.0f ? 0.5f * d * d : d - 0.5f;
}

__device__ __forceinline__ void do_force(int lane, int b, int A, int M) {
    size_t off = (size_t)b * A;
    unsigned long long pk = (lane < M) ? g_gtpack[b * MAXM + lane] : 0ull;
    if (lane < MAXM) g_gtpack[b * MAXM + lane] = 0ull;
    float    v  = __uint_as_float((unsigned)(pk >> 32));
    unsigned ba = ~((unsigned)pk);
    bool valid  = (lane < M) && (v > 1e-5f);

    unsigned key = valid ? ba : (0x80000000u + (unsigned)lane);
    unsigned grp = __match_any_sync(0xffffffffu, key);

    unsigned char oldpos = valid ? g_pos[off + ba] : (unsigned char)1;
    float ab = valid ? g_abest[off + ba] : 1e30f;
    bool over = valid && (ab < v);
    unsigned ovm = __ballot_sync(0xffffffffu, over);
    if (over && (31 - __clz(grp & ovm)) == lane) g_aidx[off + ba] = lane;
    if (valid) g_pos[off + ba] = 1;

    bool newpos = valid && !oldpos && ((__ffs(grp) - 1) == lane);
    unsigned nm = __ballot_sync(0xffffffffu, newpos);

    int pc = (lane < SCH) ? g_pcnt[b * SCH + lane] : 0;
    #pragma unroll
    for (int o = 16; o; o >>= 1) pc += __shfl_xor_sync(0xffffffffu, pc, o);
    if (lane == 0) g_npos[b] = pc + __popc(nm);
}

// ---------------------------------------------------------------------------
// kbig: heterogeneous blocks (match interleaved into loss stream).
// ---------------------------------------------------------------------------
__global__ void __launch_bounds__(256, 5)
kbig(const float* __restrict__ scores, const float* __restrict__ gtb,
     const float* __restrict__ anc, int A, int M, int gx,
     int chunk1, int chunkA, int ngj, int S, int Mt, int M1, int Tm) {
    __shared__ union {
        struct { float tile[128 * 81]; float sPart[128]; } ls;
        struct { float4 sg[MAXM]; float sga[MAXM]; int scnt[256]; int lastFlag; } m1;
        struct { float4 sg[NGT]; float sga[NGT]; unsigned long long sred[256]; int lastFlag; } m2;
    } sm;

    int p   = blockIdx.x;
    int tid = threadIdx.x;
    int lim = S * Mt;
    bool isMatch = (p < lim) && (p % S == 0) && (p / S < Mt);
    int idx = isMatch ? (p / S) : ((p < lim) ? (p - p / S - 1) : (p - Mt));

    if (isMatch && idx < M1) {
        int b  = idx / SCH;
        int bx = idx % SCH;
        if (tid < MAXM) {
            float4 g = make_float4(-9.0f, -9.0f, -9.0f, -9.0f);
            if (tid < M) g = ((const float4*)gtb)[b * M + tid];
            sm.m1.sg[tid]  = g;
            sm.m1.sga[tid] = (g.z - g.x) * (g.w - g.y);
        }
        __syncthreads();
        size_t off = (size_t)b * A;
        int a0 = bx * chunk1;
        int a1 = a0 + chunk1; if (a1 > A) a1 = A;
        int cnt = 0;
        for (int a = a0 + tid; a < a1; a += 256) {
            float4 ac = __ldg(((const float4*)anc) + a);
            float aw2 = ac.z * 0.5f, ah2 = ac.w * 0.5f;
            float ax1 = ac.x - aw2, ay1 = ac.y - ah2;
            float ax2 = ac.x + aw2, ay2 = ac.y + ah2;
            float areaA = (ax2 - ax1) * (ay2 - ay1);
            float best = -1.0f; int bidx = 0;
            #pragma unroll
            for (int j = 0; j < MAXM; j++) {
                float4 g = sm.m1.sg[j];
                float ltx = fmaxf(g.x, ax1), lty = fmaxf(g.y, ay1);
                float rbx = fminf(g.z, ax2), rby = fminf(g.w, ay2);
                float w = fmaxf(rbx - ltx, 0.0f), h = fmaxf(rby - lty, 0.0f);
                float inter = w * h;
                float iou = __fdividef(inter, sm.m1.sga[j] + areaA - inter + 1e-7f);
                bool bw = iou > best;
                best = bw ? iou : best;
                bidx = bw ? j : bidx;
            }
            g_abest[off + a] = best;
            g_aidx[off + a]  = bidx;
            unsigned char pp = best > 0.5f ? (unsigned char)1 : (unsigned char)0;
            g_pos[off + a] = pp;
            cnt += pp;
        }
        sm.m1.scnt[tid] = cnt;
        __syncthreads();
        for (int s = 128; s > 0; s >>= 1) {
            if (tid < s) sm.m1.scnt[tid] += sm.m1.scnt[tid + s];
            __syncthreads();
        }
        if (tid == 0) g_pcnt[b * SCH + bx] = sm.m1.scnt[0];
        __threadfence();
        if (tid == 0)
            sm.m1.lastFlag = (atomicAdd(&g_cnt[b], 1) == Tm - 1) ? 1 : 0;
        __syncthreads();
        if (sm.m1.lastFlag) {
            if (tid == 0) g_cnt[b] = 0;
            if (tid < 32) do_force(tid, b, A, M);
        }
    } else if (isMatch) {
        int idx2 = idx - M1;
        int pb   = ngj * TCH;
        int b    = idx2 / pb;
        int q    = idx2 % pb;
        int jg   = q % ngj;
        int tch  = q / ngj;
        int j0   = jg * NGT;
        if (tid < NGT) {
            int j = j0 + tid;
            float4 g = make_float4(-9.0f, -9.0f, -9.0f, -9.0f);
            if (j < M) g = ((const float4*)gtb)[b * M + j];
            sm.m2.sg[tid]  = g;
            sm.m2.sga[tid] = (g.z - g.x) * (g.w - g.y);
        }
        __syncthreads();
        float bv0 = -1.0f, bv1 = -1.0f, bv2 = -1.0f, bv3 = -1.0f;
        unsigned bi0 = 0, bi1 = 0, bi2 = 0, bi3 = 0;
        float4 g0 = sm.m2.sg[0], g1 = sm.m2.sg[1], g2 = sm.m2.sg[2], g3 = sm.m2.sg[3];
        float a0v = sm.m2.sga[0], a1v = sm.m2.sga[1], a2v = sm.m2.sga[2], a3v = sm.m2.sga[3];

        int as = tch * chunkA;
        int ae = as + chunkA; if (ae > A) ae = A;
        for (int a = as + tid; a < ae; a += 256) {
            float4 ac = __ldg(((const float4*)anc) + a);
            float aw2 = ac.z * 0.5f, ah2 = ac.w * 0.5f;
            float ax1 = ac.x - aw2, ay1 = ac.y - ah2;
            float ax2 = ac.x + aw2, ay2 = ac.y + ah2;
            float areaA = (ax2 - ax1) * (ay2 - ay1);
            #define IOU_OF(G, AREA, BV, BI)                                    \
            {                                                                  \
                float ltx = fmaxf(G.x, ax1), lty = fmaxf(G.y, ay1);            \
                float rbx = fminf(G.z, ax2), rby = fminf(G.w, ay2);            \
                float w = fmaxf(rbx - ltx, 0.0f), h = fmaxf(rby - lty, 0.0f);  \
                float inter = w * h;                                           \
                float iou = __fdividef(inter, AREA + areaA - inter + 1e-7f);   \
                if (iou > BV) { BV = iou; BI = (unsigned)a; }                  \
            }
            IOU_OF(g0, a0v, bv0, bi0)
            IOU_OF(g1, a1v, bv1, bi1)
            IOU_OF(g2, a2v, bv2, bi2)
            IOU_OF(g3, a3v, bv3, bi3)
            #undef IOU_OF
        }
        float    bvs[NGT] = {bv0, bv1, bv2, bv3};
        unsigned bis[NGT] = {bi0, bi1, bi2, bi3};
        #pragma unroll
        for (int g = 0; g < NGT; g++) {
            unsigned long long pk =
                ((unsigned long long)__float_as_uint(bvs[g]) << 32) | (unsigned)(~bis[g]);
            sm.m2.sred[tid] = pk;
            __syncthreads();
            for (int s = 128; s > 0; s >>= 1) {
                if (tid < s) {
                    unsigned long long o = sm.m2.sred[tid + s];
                    if (o > sm.m2.sred[tid]) sm.m2.sred[tid] = o;
                }
                __syncthreads();
            }
            if (tid == 0 && j0 + g < M)
                atomicMax(&g_gtpack[b * MAXM + j0 + g], sm.m2.sred[0]);
            __syncthreads();
        }
        __threadfence();
        if (tid == 0)
            sm.m2.lastFlag = (atomicAdd(&g_cnt[b], 1) == Tm - 1) ? 1 : 0;
        __syncthreads();
        if (sm.m2.lastFlag) {
            if (tid == 0) g_cnt[b] = 0;
            if (tid < 32) do_force(tid, b, A, M);
        }
    } else {
        const int NC = 81;
        int b = idx / gx;
        int t = idx % gx;
        int abase = t * 128;
        int cnt = A - abase; if (cnt > 128) cnt = 128;
        size_t off  = (size_t)b * A;
        size_t base = (off + (size_t)abase) * NC;
        int nflt = cnt * NC;
        float* tile = sm.ls.tile;

        const float* src = scores + base;
        if ((base & 3) == 0) {
            const float4* s4 = (const float4*)src;
            float4* t4 = (float4*)tile;
            int n4 = nflt >> 2;
            for (int i = tid; i < n4; i += 256) {
                float4 v = __ldg(s4 + i);
                v.x = __expf(v.x); v.y = __expf(v.y);
                v.z = __expf(v.z); v.w = __expf(v.w);
                t4[i] = v;
            }
            for (int i = (n4 << 2) + tid; i < nflt; i += 256) tile[i] = __expf(src[i]);
        } else {
            for (int i = tid; i < nflt; i += 256) tile[i] = __expf(__ldg(src + i));
        }
        __syncthreads();

        int r    = tid & 127;
        int half = tid >> 7;
        float mySum = 0.0f;
        if (r < cnt) {
            const float* row = tile + r * NC;
            float s0 = 0, s1 = 0, s2 = 0, s3 = 0;
            if (half == 0) {
                #pragma unroll
                for (int c = 0; c < 40; c += 4) {
                    s0 += row[c]; s1 += row[c + 1]; s2 += row[c + 2]; s3 += row[c + 3];
                }
                s0 += row[40];
            } else {
                #pragma unroll
                for (int c = 41; c < 81; c += 4) {
                    s0 += row[c]; s1 += row[c + 1]; s2 += row[c + 2]; s3 += row[c + 3];
                }
            }
            mySum = (s0 + s1) + (s2 + s3);
            if (half == 1) sm.ls.sPart[r] = mySum;
        }
        __syncthreads();
        if (half == 0 && r < cnt) {
            float s = mySum + sm.ls.sPart[r];
            float conf0 = __logf(s) - __logf(tile[r * NC]);
            g_negkey[off + abase + r] = f2key(conf0);
        }
    }
}

// ---------------------------------------------------------------------------
// kfixhist: vectorized (4 anchors/thread/iter). Fix positives + 4096-bin hist.
// Grid (FCH, B), 256 threads. chunk must be a multiple of 4.
// ---------------------------------------------------------------------------
__global__ void __launch_bounds__(256)
kfixhist(const float* __restrict__ scores, const float* __restrict__ plocs,
         const float* __restrict__ gtb, const int* __restrict__ gtl,
         const float* __restrict__ anc, int A, int M, int C, int chunk) {
    __shared__ unsigned int sh[HBINS];
    __shared__ float sL[256], sC[256];
    int b   = blockIdx.y;
    int tid = threadIdx.x;
    for (int i = tid; i < HBINS; i += 256) sh[i] = 0u;
    __syncthreads();

    size_t off = (size_t)b * A;
    int a0 = blockIdx.x * chunk;
    int a1 = a0 + chunk; if (a1 > A) a1 = A;
    float loc = 0.0f, cp = 0.0f;

    #define FIXUP(aa, key)                                                      \
    {                                                                           \
        g_negkey[off + (aa)] = 0u;                                              \
        int ai  = g_aidx[off + (aa)];                                           \
        int cls = __ldg(gtl + (size_t)b * M + ai) + 1;                          \
        const float* sp = scores + (off + (aa)) * (size_t)C;                    \
        float conf = key2f(key) + __ldg(sp) - __ldg(sp + cls);                  \
        cp += conf;                                                             \
        float4 pl  = __ldg(((const float4*)plocs) + off + (aa));                \
        float4 ac4 = __ldg(((const float4*)anc) + (aa));                        \
        float4 g   = __ldg(((const float4*)gtb) + (size_t)b * M + ai);          \
        float mcx = (g.x + g.z) * 0.5f, mcy = (g.y + g.w) * 0.5f;               \
        float mw = g.z - g.x, mh = g.w - g.y;                                   \
        loc += sl1(pl.x - (mcx - ac4.x) / ac4.z)                                \
             + sl1(pl.y - (mcy - ac4.y) / ac4.w)                                \
             + sl1(pl.z - logf(mw / ac4.z + 1e-7f))                             \
             + sl1(pl.w - logf(mh / ac4.w + 1e-7f));                            \
    }

    if (((a0 | a1) & 3) == 0 && ((off & 3) == 0)) {
        const uint4*  k4 = (const uint4*)(g_negkey + off);
        const uchar4* p4 = (const uchar4*)(g_pos + off);
        int i0 = a0 >> 2, i1 = a1 >> 2;
        for (int i = i0 + tid; i < i1; i += 256) {
            uint4  kv = k4[i];
            uchar4 pv = p4[i];
            int a = i << 2;
            unsigned b0 = pv.x ? 0u : (kv.x >> 20);
            unsigned b1 = pv.y ? 0u : (kv.y >> 20);
            unsigned b2 = pv.z ? 0u : (kv.z >> 20);
            unsigned b3 = pv.w ? 0u : (kv.w >> 20);
            atomicAdd(&sh[b0], 1u); atomicAdd(&sh[b1], 1u);
            atomicAdd(&sh[b2], 1u); atomicAdd(&sh[b3], 1u);
            if (pv.x && kv.x) FIXUP(a + 0, kv.x)
            if (pv.y && kv.y) FIXUP(a + 1, kv.y)
            if (pv.z && kv.z) FIXUP(a + 2, kv.z)
            if (pv.w && kv.w) FIXUP(a + 3, kv.w)
        }
    } else {
        for (int a = a0 + tid; a < a1; a += 256) {
            unsigned key = g_negkey[off + a];
            unsigned char p = g_pos[off + a];
            unsigned bin = p ? 0u : (key >> 20);
            atomicAdd(&sh[bin], 1u);
            if (p && key) FIXUP(a, key)
        }
    }
    #undef FIXUP

    __syncthreads();
    for (int i = tid; i < HBINS; i += 256) {
        unsigned v = sh[i];
        if (v) atomicAdd(&g_hist2[b * HBINS + i], v);
    }
    sL[tid] = loc; sC[tid] = cp;
    __syncthreads();
    for (int s = 128; s > 0; s >>= 1) {
        if (tid < s) { sL[tid] += sL[tid + s]; sC[tid] += sC[tid + s]; }
        __syncthreads();
    }
    if (tid == 0) {
        int pid = b * FCH + blockIdx.x;
        g_ploc2[pid]  = sL[0];
        g_pconf2[pid] = sC[0];
    }
}

// Generic fallback (C != 81).
template <int NSEG>
__global__ void __launch_bounds__(256)
klossg(const float* __restrict__ plocs, const float* __restrict__ scores,
       const float* __restrict__ gtb, const int* __restrict__ gtl,
       const float* __restrict__ anc, int A, int M, int C) {
    const float NEG = -1e30f;
    int b    = blockIdx.y;
    int warp = threadIdx.x >> 5;
    int lane = threadIdx.x & 31;
    size_t off = (size_t)b * A;
    int abase = (blockIdx.x * 8 + warp) * 8;
    float locSum = 0.0f, confPos = 0.0f;

    for (int k = 0; k < 8; k++) {
        int a = abase + k;
        if (a >= A) break;
        const float* sp = scores + (off + a) * (size_t)C;
        float v[NSEG]; float m;
        #pragma unroll
        for (int sgi = 0; sgi < NSEG; sgi++) {
            int c = lane + sgi * 32;
            v[sgi] = (c < C) ? __ldg(sp + c) : NEG;
        }
        m = v[0];
        #pragma unroll
        for (int sgi = 1; sgi < NSEG; sgi++) m = fmaxf(m, v[sgi]);
        #pragma unroll
        for (int o = 16; o; o >>= 1) m = fmaxf(m, __shfl_xor_sync(0xffffffffu, m, o));
        float s = 0.0f;
        #pragma unroll
        for (int sgi = 0; sgi < NSEG; sgi++) s += __expf(v[sgi] - m);
        #pragma unroll
        for (int o = 16; o; o >>= 1) s += __shfl_xor_sync(0xffffffffu, s, o);

        unsigned char p = g_pos[off + a];
        int ai = g_aidx[off + a];
        int cls = p ? (__ldg(gtl + (size_t)b * M + ai) + 1) : 0;
        int slot = cls >> 5, src = cls & 31;
        float vv = v[0];
        #pragma unroll
        for (int sgi = 1; sgi < NSEG; sgi++) if (slot == sgi) vv = v[sgi];
        float xt = __shfl_sync(0xffffffffu, vv, src);
        float conf = m + __logf(s) - xt;
        if (lane == 0) {
            g_negkey[off + a] = p ? 0u : f2key(conf);
            if (p) {
                confPos += conf;
                float4 pl  = __ldg(((const float4*)plocs) + off + a);
                float4 ac4 = __ldg(((const float4*)anc) + a);
                float4 g   = __ldg(((const float4*)gtb) + (size_t)b * M + ai);
                float mcx = (g.x + g.z) * 0.5f, mcy = (g.y + g.w) * 0.5f;
                float mw = g.z - g.x, mh = g.w - g.y;
                locSum += sl1(pl.x - (mcx - ac4.x) / ac4.z)
                        + sl1(pl.y - (mcy - ac4.y) / ac4.w)
                        + sl1(pl.z - logf(mw / ac4.z + 1e-7f))
                        + sl1(pl.w - logf(mh / ac4.w + 1e-7f));
            }
        }
    }
    __shared__ float smL[8], smC[8];
    if (lane == 0) { smL[warp] = locSum; smC[warp] = confPos; }
    __syncthreads();
    if (threadIdx.x == 0) {
        float L = 0.0f, Cc = 0.0f;
        #pragma unroll
        for (int i = 0; i < 8; i++) { L += smL[i]; Cc += smC[i]; }
        g_ploc[blockIdx.y * gridDim.x + blockIdx.x]  = L;
        g_pconf[blockIdx.y * gridDim.x + blockIdx.x] = Cc;
    }
}

// ---------------------------------------------------------------------------
// kselect2: exact top-k sum. 1024 threads; uint4 key streaming (high MLP).
// Self-cleans g_hist2.
// ---------------------------------------------------------------------------
__global__ void __launch_bounds__(1024)
kselect2(int A) {
    extern __shared__ unsigned int sbuf[];
    __shared__ unsigned int hist[HBINS];
    __shared__ unsigned int coarse[1024];
    __shared__ float red[1024];
    __shared__ unsigned int s_d, s_kk, s_cnt, s_prefix, s_kk2;
    __shared__ unsigned int h2[256];

    int b   = blockIdx.x;
    int tid = threadIdx.x;
    size_t off = (size_t)b * A;

    for (int i = tid; i < HBINS; i += 1024) {
        hist[i] = g_hist2[b * HBINS + i];
        g_hist2[b * HBINS + i] = 0u;
    }
    __syncthreads();

    int np = g_npos[b];
    int k;
    if (np > 0) { k = 3 * np; int lim = A - np; if (k > lim) k = lim; }
    else        { k = (60 < A) ? 60 : A; }
    if (k <= 0) { if (tid == 0) g_topk[b] = 0.0f; return; }

    {
        unsigned s = 0;
        #pragma unroll
        for (int j = 0; j < 4; j++) s += hist[tid * 4 + j];
        coarse[tid] = s;
    }
    __syncthreads();
    for (int o = 1; o < 1024; o <<= 1) {
        unsigned v = (tid + o < 1024) ? coarse[tid + o] : 0u;
        __syncthreads();
        coarse[tid] += v;
        __syncthreads();
    }
    {
        unsigned suf = coarse[tid];
        unsigned nxt = (tid < 1023) ? coarse[tid + 1] : 0u;
        if (suf >= (unsigned)k && nxt < (unsigned)k) {
            unsigned cum = nxt;
            int d = tid * 4;
            for (int bin = tid * 4 + 3; bin >= tid * 4; bin--) {
                cum += hist[bin];
                if (cum >= (unsigned)k) { d = bin; break; }
            }
            s_d  = (unsigned)d;
            s_kk = (unsigned)k - (cum - hist[d]);
        }
        if (tid == 0) s_cnt = 0u;
    }
    __syncthreads();
    unsigned d  = s_d;
    unsigned kk = s_kk;
    unsigned nBoundary = hist[d];

    float sum = 0.0f;
    bool fits = nBoundary <= CAP;
    if (((A & 3) == 0) && fits) {
        // vectorized stream: 4 keys per load, loop unrollable (no cross-iter dep)
        const uint4* k4 = (const uint4*)(g_negkey + off);
        int n4 = A >> 2;
        #pragma unroll 2
        for (int i = tid; i < n4; i += 1024) {
            uint4 kv = k4[i];
            #define PROC(KK)                                                    \
            {                                                                   \
                unsigned bin = (KK) >> 20;                                      \
                if (bin > d) sum += key2f(KK);                                  \
                else if (bin == d) sbuf[atomicAdd(&s_cnt, 1u)] = (KK);          \
            }
            PROC(kv.x) PROC(kv.y) PROC(kv.z) PROC(kv.w)
            #undef PROC
        }
    } else {
        for (int i = tid; i < A; i += 1024) {
            unsigned key = g_negkey[off + i];
            unsigned bin = key >> 20;
            if (bin > d) sum += key2f(key);
            else if (bin == d && fits) sbuf[atomicAdd(&s_cnt, 1u)] = key;
        }
    }
    __syncthreads();

    unsigned prefix = d << 20, maskHi = 0xFFF00000u;
    if (fits) {
        unsigned n = s_cnt;
        #pragma unroll
        for (int p = 0; p < 3; p++) {
            int shift = (p == 0) ? 12 : (p == 1) ? 4 : 0;
            unsigned bmask = (p == 2) ? 15u : 255u;
            int nb = (p == 2) ? 16 : 256;
            if (tid < 256) h2[tid] = 0u;
            __syncthreads();
            for (unsigned i = tid; i < n; i += 1024) {
                unsigned key = sbuf[i];
                if ((key & maskHi) == prefix)
                    atomicAdd(&h2[(key >> shift) & bmask], 1u);
            }
            __syncthreads();
            if (tid == 0) {
                unsigned cum = 0; int dd = nb - 1;
                for (; dd >= 0; dd--) { cum += h2[dd]; if (cum >= kk) break; }
                s_kk2    = kk - (cum - h2[dd]);
                s_prefix = prefix | ((unsigned)dd << shift);
            }
            __syncthreads();
            prefix = s_prefix;
            kk     = s_kk2;
            maskHi |= bmask << shift;
            __syncthreads();
        }
        for (unsigned i = tid; i < n; i += 1024) {
            unsigned key = sbuf[i];
            if (key > prefix) sum += key2f(key);
        }
    } else {
        #pragma unroll
        for (int p = 0; p < 3; p++) {
            int shift = (p == 0) ? 12 : (p == 1) ? 4 : 0;
            unsigned bmask = (p == 2) ? 15u : 255u;
            int nb = (p == 2) ? 16 : 256;
            if (tid < 256) h2[tid] = 0u;
            __syncthreads();
            for (int i = tid; i < A; i += 1024) {
                unsigned key = g_negkey[off + i];
                if ((key & maskHi) == prefix)
                    atomicAdd(&h2[(key >> shift) & bmask], 1u);
            }
            __syncthreads();
            if (tid == 0) {
                unsigned cum = 0; int dd = nb - 1;
                for (; dd >= 0; dd--) { cum += h2[dd]; if (cum >= kk) break; }
                s_kk2    = kk - (cum - h2[dd]);
                s_prefix = prefix | ((unsigned)dd << shift);
            }
            __syncthreads();
            prefix = s_prefix;
            kk     = s_kk2;
            maskHi |= bmask << shift;
            __syncthreads();
        }
        for (int i = tid; i < A; i += 1024) {
            unsigned key = g_negkey[off + i];
            if ((key >> 20) == d && key > prefix) sum += key2f(key);
        }
    }
    if (tid == 0) sum += (float)kk * key2f(prefix);

    red[tid] = sum;
    __syncthreads();
    for (int s = 512; s > 0; s >>= 1) {
        if (tid < s) red[tid] += red[tid + s];
        __syncthreads();
    }
    if (tid == 0) g_topk[b] = red[0];
}

// ---------------------------------------------------------------------------
__global__ void knop() {
    if (threadIdx.x < MAX_B) g_cnt[threadIdx.x] = 0;
}

__global__ void kfinal(float* __restrict__ out, int P1, int P2, int B) {
    __shared__ float s1[512], s2[512];
    __shared__ int   s3[512];
    int tid = threadIdx.x;
    float L = 0.0f, Cc = 0.0f; int np = 0;
    for (int i = tid; i < P1; i += 512) { L += g_ploc[i];  Cc += g_pconf[i];  }
    for (int i = tid; i < P2; i += 512) { L += g_ploc2[i]; Cc += g_pconf2[i]; }
    for (int i = tid; i < B;  i += 512) { Cc += g_topk[i]; np += g_npos[i];   }
    s1[tid] = L; s2[tid] = Cc; s3[tid] = np;
    __syncthreads();
    for (int s = 256; s > 0; s >>= 1) {
        if (tid < s) { s1[tid] += s1[tid+s]; s2[tid] += s2[tid+s]; s3[tid] += s3[tid+s]; }
        __syncthreads();
    }
    if (tid == 0) {
        float loc = s1[0], conf = s2[0];
        float denom = (float)(s3[0] > 1 ? s3[0] : 1);
        out[0] = (loc + conf) / denom;
        out[1] = loc / denom;
        out[2] = conf / denom;
    }
}

// ---------------------------------------------------------------------------
extern "C" void kernel_launch(void* const* d_in, const int* in_sizes, int n_in,
                              void* d_out, int out_size) {
    const float* plocs  = (const float*)d_in[0];
    const float* scores = (const float*)d_in[1];
    const float* gtb    = (const float*)d_in[2];
    const int*   gtl    = (const int*)d_in[3];
    const float* anc    = (const float*)d_in[4];

    int A = in_sizes[4] / 4;
    int B = in_sizes[0] / (4 * A);
    int C = (int)((long long)in_sizes[1] / ((long long)A * B));
    int M = in_sizes[3] / B;

    int gx81   = (A + 127) / 128;
    int L      = (C == 81) ? gx81 * B : 0;
    int ngj    = (M + NGT - 1) / NGT;
    int Tm     = SCH + ngj * TCH;
    int Mt     = Tm * B;
    int total  = L + Mt;
    int S      = total / Mt; if (S < 1) S = 1;
    int chunk1 = (A + SCH - 1) / SCH;
    int chunkA = (A + TCH - 1) / TCH;
    int M1     = SCH * B;

    knop<<<1, 64>>>();                                               // 1
    kbig<<<total, 256>>>(scores, gtb, anc, A, M, gx81,
                         chunk1, chunkA, ngj, S, Mt, M1, Tm);        // 2

    int P1 = 0;
    if (C != 81) {
        int gxg = (A + 63) / 64;
        if (C <= 96) klossg<3><<<dim3(gxg, B), 256>>>(plocs, scores, gtb, gtl, anc, A, M, C);
        else         klossg<4><<<dim3(gxg, B), 256>>>(plocs, scores, gtb, gtl, anc, A, M, C);
        P1 = gxg * B;
    }

    int fch = ((A + FCH - 1) / FCH + 3) & ~3;                        // multiple of 4
    kfixhist<<<dim3(FCH, B), 256>>>(scores, plocs, gtb, gtl, anc, A, M, C, fch); // 3

    cudaFuncSetAttribute(kselect2, cudaFuncAttributeMaxDynamicSharedMemorySize,
                         CAP * 4 + 1024);
    kselect2<<<B, 1024, CAP * 4>>>(A);                               // 4 (profiled)

    kfinal<<<1, 512>>>((float*)d_out, P1, FCH * B, B);               // 5
}